// round 1
// baseline (speedup 1.0000x reference)
#include <cuda_runtime.h>
#include <cstdint>

#define B_ 8
#define C_ 16
#define H_ 224
#define W_ 224
#define T_ 8
#define N_ 5
#define NEGV (-1e30f)
#define NTOT (B_*C_*H_*W_)

// Scratch: xv = log1p(relu(x)), computed once, reused by all 8 trees per plane.
__device__ float g_xv[NTOT];

__global__ void xv_kernel(const float* __restrict__ x) {
    int n4 = NTOT / 4;
    for (int i = blockIdx.x * blockDim.x + threadIdx.x; i < n4;
         i += gridDim.x * blockDim.x) {
        float4 v = reinterpret_cast<const float4*>(x)[i];
        v.x = log1pf(fmaxf(v.x, 0.f));
        v.y = log1pf(fmaxf(v.y, 0.f));
        v.z = log1pf(fmaxf(v.z, 0.f));
        v.w = log1pf(fmaxf(v.w, 0.f));
        reinterpret_cast<float4*>(g_xv)[i] = v;
    }
}

struct Forest { int par[T_][N_]; };

// cummax update: M <- cummax_w( max(M, v) )  across 224 columns
// (28 active lanes x 8 cols). Valid since M is nondecreasing in w.
__device__ __forceinline__ void scan_update(const float v[8], float M[8], int lane) {
    float u[8];
#pragma unroll
    for (int l = 0; l < 8; l++) u[l] = fmaxf(M[l], v[l]);
#pragma unroll
    for (int l = 1; l < 8; l++) u[l] = fmaxf(u[l], u[l - 1]);
    float tot = u[7];
#pragma unroll
    for (int d = 1; d < 32; d <<= 1) {
        float o = __shfl_up_sync(0xffffffffu, tot, d);  // self for lane<d -> no-op
        tot = fmaxf(tot, o);
    }
    float excl = __shfl_up_sync(0xffffffffu, tot, 1);
    if (lane == 0) excl = NEGV;
#pragma unroll
    for (int l = 0; l < 8; l++) M[l] = fmaxf(u[l], excl);
}

__global__ void __launch_bounds__(32)
forest_kernel(const float* __restrict__ alphas, float* __restrict__ out, Forest f) {
    const unsigned FULL = 0xffffffffu;
    int blk = blockIdx.x;
    int t = blk & 7;
    int c = (blk >> 3) & 15;
    int b = blk >> 7;
    int lane = threadIdx.x;
    const float* plane = g_xv + (size_t)(b * C_ + c) * (H_ * W_);

    float a[N_];
#pragma unroll
    for (int i = 0; i < N_; i++) a[i] = alphas[(t * N_ + i) * C_ + c];

    const int p2 = f.par[t][2], p3 = f.par[t][3], p4 = f.par[t][4];
    // p1 is always 0 (integers(0,1) == 0)

    // M[j] = inclusive 2D cummax of node j+1 (children nodes are 1..4),
    // rows processed so far. Per-lane chunk of 8 columns.
    float M[4][8];
#pragma unroll
    for (int j = 0; j < 4; j++)
#pragma unroll
        for (int l = 0; l < 8; l++) M[j][l] = NEGV;

    float runmax = NEGV;
    const bool act = lane < 28;
    const int col0 = lane * 8;

    for (int h = 0; h < H_; h++) {
        float xv[8];
        if (act) {
            float4 r0 = *reinterpret_cast<const float4*>(plane + h * W_ + col0);
            float4 r1 = *reinterpret_cast<const float4*>(plane + h * W_ + col0 + 4);
            xv[0] = r0.x; xv[1] = r0.y; xv[2] = r0.z; xv[3] = r0.w;
            xv[4] = r1.x; xv[5] = r1.y; xv[6] = r1.z; xv[7] = r1.w;
        } else {
#pragma unroll
            for (int l = 0; l < 8; l++) xv[l] = NEGV;
        }

        // Shifted previous-row M: ms[j][w] = M_old[j][w-1] (NEG at w==0).
        // Captured BEFORE any update this row (s uses rows < h strictly).
        float ms[4][8];
#pragma unroll
        for (int j = 0; j < 4; j++) {
            float up = __shfl_up_sync(FULL, M[j][7], 1);
            ms[j][0] = (lane == 0) ? NEGV : up;
#pragma unroll
            for (int l = 1; l < 8; l++) ms[j][l] = M[j][l - 1];
        }

        float v[8];
        // ---- node 4 (no children possible) ----
#pragma unroll
        for (int l = 0; l < 8; l++) v[l] = xv[l] + a[4];
        scan_update(v, M[3], lane);

        // ---- node 3 (possible child: 4) ----
#pragma unroll
        for (int l = 0; l < 8; l++) v[l] = xv[l] + a[3];
        if (p4 == 3) {
#pragma unroll
            for (int l = 0; l < 8; l++) v[l] += ms[3][l];
        }
        scan_update(v, M[2], lane);

        // ---- node 2 (possible children: 3,4) ----
#pragma unroll
        for (int l = 0; l < 8; l++) v[l] = xv[l] + a[2];
        if (p3 == 2) {
#pragma unroll
            for (int l = 0; l < 8; l++) v[l] += ms[2][l];
        }
        if (p4 == 2) {
#pragma unroll
            for (int l = 0; l < 8; l++) v[l] += ms[3][l];
        }
        scan_update(v, M[1], lane);

        // ---- node 1 (possible children: 2,3,4) ----
#pragma unroll
        for (int l = 0; l < 8; l++) v[l] = xv[l] + a[1];
        if (p2 == 1) {
#pragma unroll
            for (int l = 0; l < 8; l++) v[l] += ms[1][l];
        }
        if (p3 == 1) {
#pragma unroll
            for (int l = 0; l < 8; l++) v[l] += ms[2][l];
        }
        if (p4 == 1) {
#pragma unroll
            for (int l = 0; l < 8; l++) v[l] += ms[3][l];
        }
        scan_update(v, M[0], lane);

        // ---- root node 0: node 1 is always a child ----
#pragma unroll
        for (int l = 0; l < 8; l++) v[l] = xv[l] + a[0] + ms[0][l];
        if (p2 == 0) {
#pragma unroll
            for (int l = 0; l < 8; l++) v[l] += ms[1][l];
        }
        if (p3 == 0) {
#pragma unroll
            for (int l = 0; l < 8; l++) v[l] += ms[2][l];
        }
        if (p4 == 0) {
#pragma unroll
            for (int l = 0; l < 8; l++) v[l] += ms[3][l];
        }
#pragma unroll
        for (int l = 0; l < 8; l++) runmax = fmaxf(runmax, v[l]);
    }

#pragma unroll
    for (int d = 16; d; d >>= 1)
        runmax = fmaxf(runmax, __shfl_xor_sync(FULL, runmax, d));
    if (lane == 0)
        out[(b * T_ + t) * C_ + c] = expm1f(runmax);
}

// ============================================================================
// Host: exact replication of np.random.default_rng(0) draws used by
// make_forest(): SeedSequence(0) -> PCG64 (XSL-RR 128/64) -> Generator
// .integers(0, i) (Lemire, buffered 32-bit path) for i = 1..4 per tree.
// ============================================================================

static inline uint32_t hashmix_(uint32_t v, uint32_t* hc) {
    v ^= *hc;
    *hc *= 0x931e8875u;   // MULT_A
    v *= *hc;
    v ^= v >> 16;
    return v;
}
static inline uint32_t mix_(uint32_t x, uint32_t y) {
    uint32_t r = x * 0xca01f9ddu - y * 0x4973f715u;  // MIX_MULT_L/R
    r ^= r >> 16;
    return r;
}

static void compute_forest(Forest* f) {
    // SeedSequence(0): entropy = [0]
    uint32_t pool[4];
    uint32_t hc = 0x43b0d7e5u;  // INIT_A
    for (int i = 0; i < 4; i++) pool[i] = hashmix_(0u, &hc);  // entropy[0]=0, rest pad 0
    for (int s = 0; s < 4; s++)
        for (int d = 0; d < 4; d++)
            if (s != d) pool[d] = mix_(pool[d], hashmix_(pool[s], &hc));

    // generate_state(4, uint64) -> 8 uint32 words
    uint32_t hb = 0x8b51f9ddu;  // INIT_B
    uint32_t w32[8];
    for (int i = 0; i < 8; i++) {
        uint32_t dv = pool[i & 3];
        dv ^= hb;
        hb *= 0x58f38dedu;  // MULT_B
        dv *= hb;
        dv ^= dv >> 16;
        w32[i] = dv;
    }
    uint64_t val[4];
    for (int i = 0; i < 4; i++)
        val[i] = (uint64_t)w32[2 * i] | ((uint64_t)w32[2 * i + 1] << 32);

    // PCG64 seeding: initstate = (val0<<64)|val1, initseq = (val2<<64)|val3
    typedef unsigned __int128 u128;
    const u128 MULT = ((u128)2549297995355413924ULL << 64) | 4865540595714422341ULL;
    u128 initstate = ((u128)val[0] << 64) | (u128)val[1];
    u128 inc = (((((u128)val[2] << 64) | (u128)val[3])) << 1) | 1;
    u128 state = inc;        // state = 0*MULT + inc
    state += initstate;
    state = state * MULT + inc;

    int has32 = 0;
    uint32_t cached = 0;

    for (int t = 0; t < T_; t++) {
        f->par[t][0] = -1;
        f->par[t][1] = 0;  // integers(0,1): rng==0, no draw consumed
        for (int i = 2; i < N_; i++) {
            uint32_t rng = (uint32_t)i - 1u;   // inclusive upper bound
            uint32_t rng_excl = rng + 1u;
            uint64_t m;
            uint32_t leftover;
            for (;;) {
                uint32_t r32;
                if (has32) {
                    has32 = 0;
                    r32 = cached;
                } else {
                    state = state * MULT + inc;  // step, then output (XSL-RR)
                    uint64_t hi = (uint64_t)(state >> 64);
                    uint64_t lo = (uint64_t)state;
                    unsigned rot = (unsigned)(uint64_t)(state >> 122);
                    uint64_t x = hi ^ lo;
                    uint64_t o = (x >> rot) | (x << ((64u - rot) & 63u));
                    has32 = 1;
                    cached = (uint32_t)(o >> 32);  // high word buffered
                    r32 = (uint32_t)o;             // low word first
                }
                m = (uint64_t)r32 * (uint64_t)rng_excl;
                leftover = (uint32_t)m;
                if (leftover >= rng_excl) break;
                uint32_t thr = (0xFFFFFFFFu - rng) % rng_excl;
                if (leftover >= thr) break;
            }
            f->par[t][i] = (int)(uint32_t)(m >> 32);
        }
    }
}

extern "C" void kernel_launch(void* const* d_in, const int* in_sizes, int n_in,
                              void* d_out, int out_size) {
    const float* x = (const float*)d_in[0];
    const float* alphas = (const float*)d_in[1];
    float* out = (float*)d_out;

    Forest f;
    compute_forest(&f);

    xv_kernel<<<NTOT / 4 / 256, 256>>>(x);
    forest_kernel<<<B_ * C_ * T_, 32>>>(alphas, out, f);
}